// round 14
// baseline (speedup 1.0000x reference)
#include <cuda_runtime.h>
#include <cuda_fp16.h>
#include <math.h>

// ---------------- intermediate buffers (device globals) ---------------------
__device__ unsigned int g_a1p[128 * 32 * 56 * 56];  // conv1 out, packed {hi,lo}
__device__ unsigned int g_a2p[128 * 64 * 28 * 28];  // conv2 out, packed {hi,lo}
__device__ float g_a3[128 * 128 * 14 * 14];         // conv3 out
__device__ float g_feat[128 * 512];                 // pooled features

// packed fp16 weight fragments (hi and lo planes)
// conv1: K repacked ic-fastest, padded 147 -> 160 (5 chunks)
__device__ uint4 g_w1p_h[5 * 8 * 16],  g_w1p_l[5 * 8 * 16];
__device__ uint4 g_w2p_h[9 * 8 * 32],  g_w2p_l[9 * 8 * 32];
__device__ uint4 g_w3p_h[18 * 8 * 64], g_w3p_l[18 * 8 * 64];

// ---------------- helpers ---------------------------------------------------
__device__ __forceinline__ void fsplit(float v, unsigned short& h, unsigned short& l) {
    __half hh = __float2half_rn(v);
    __half ll = __float2half_rn(v - __half2float(hh));
    h = __half_as_ushort(hh);
    l = __half_as_ushort(ll);
}
__device__ __forceinline__ unsigned int packsplit(float v) {
    unsigned short h, l;
    fsplit(v, h, l);
    return (unsigned)h | ((unsigned)l << 16);
}

#define MMAF(d, a, b0, b1)                                                      \
    asm volatile(                                                               \
        "mma.sync.aligned.m16n8k16.row.col.f32.f16.f16.f32 "                    \
        "{%0,%1,%2,%3}, {%4,%5,%6,%7}, {%8,%9}, {%0,%1,%2,%3};"                 \
        : "+f"(d[0]), "+f"(d[1]), "+f"(d[2]), "+f"(d[3])                        \
        : "r"(a.x), "r"(a.y), "r"(a.z), "r"(a.w), "r"(b0), "r"(b1))

#define MMA3F(acc, aH, aL, bH, bL)                                              \
    do {                                                                        \
        MMAF(acc, aH, bH.x, bH.y);                                              \
        MMAF(acc, aH, bL.x, bL.y);                                              \
        MMAF(acc, aL, bH.x, bH.y);                                              \
    } while (0)

__device__ __forceinline__ void cpa16(void* sdst, const void* gsrc) {
    unsigned s = (unsigned)__cvta_generic_to_shared(sdst);
    asm volatile("cp.async.cg.shared.global [%0], [%1], 16;"
                 :: "r"(s), "l"(gsrc) : "memory");
}
#define CP_COMMIT() asm volatile("cp.async.commit_group;" ::: "memory")
#define CP_WAIT0()  asm volatile("cp.async.wait_group 0;" ::: "memory")

// ---------------- weight prep ------------------------------------------------
__device__ __forceinline__ void pack_frag(const float* v, uint4& H, uint4& L) {
    unsigned short h[8], l[8];
#pragma unroll
    for (int i = 0; i < 8; i++) fsplit(v[i], h[i], l[i]);
    H.x = h[0] | (h[1] << 16); H.y = h[2] | (h[3] << 16);
    H.z = h[4] | (h[5] << 16); H.w = h[6] | (h[7] << 16);
    L.x = l[0] | (l[1] << 16); L.y = l[2] | (l[3] << 16);
    L.z = l[4] | (l[5] << 16); L.w = l[6] | (l[7] << 16);
}

__global__ void prep_w(const float* __restrict__ w1, const float* __restrict__ w2,
                       const float* __restrict__ w3) {
    int i = blockIdx.x * 256 + threadIdx.x;
    if (i < 5 * 8 * 16) {
        int chunk = i >> 7, row = (i >> 4) & 7, t = i & 15;
        int tile = t >> 3, gid = t & 7;
        int step = row >> 2, tig = row & 3;
        int oc0 = tile * 16 + gid, oc1 = oc0 + 8;
        int kl = step * 16 + tig * 2;
        float u[8];
#pragma unroll
        for (int e = 0; e < 8; e++) {
            int oc = (e & 2) ? oc1 : oc0;
            int klx = kl + ((e >> 2) ? 8 : 0) + (e & 1);
            int k = chunk * 32 + klx;  // ic-fastest: k = 3*tap + ic
            float v = 0.f;
            if (k < 147) {
                int tap = k / 3, ic = k - tap * 3;
                int kh = tap / 7, kw = tap - kh * 7;
                v = w1[oc * 147 + ic * 49 + kh * 7 + kw];
            }
            u[e] = v;
        }
        uint4 H, L;
        pack_frag(u, H, L);
        g_w1p_h[i] = H; g_w1p_l[i] = L;
    }
    if (i < 9 * 8 * 32) {
        int chunk = i >> 8, r = i & 255;
        int row = r >> 5, t = r & 31;
        int tile = t >> 3, gid = t & 7;
        int step = row >> 2, tig = row & 3;
        int oc0 = tile * 16 + gid, oc1 = oc0 + 8;
        int kl = step * 16 + tig * 2;
        float u[8];
#pragma unroll
        for (int e = 0; e < 8; e++) {
            int oc = (e & 2) ? oc1 : oc0;
            int klx = kl + ((e >> 2) ? 8 : 0) + (e & 1);
            u[e] = w2[oc * 288 + klx * 9 + chunk];
        }
        uint4 H, L;
        pack_frag(u, H, L);
        g_w2p_h[i] = H; g_w2p_l[i] = L;
    }
    if (i < 18 * 8 * 64) {
        int chunk = i >> 9, r = i & 511;
        int row = r >> 6, t = r & 63;
        int tile = t >> 3, gid = t & 7;
        int step = row >> 2, tig = row & 3;
        int oc0 = tile * 16 + gid, oc1 = oc0 + 8;
        int kl = step * 16 + tig * 2;
        int tap = chunk >> 1, icb = (chunk & 1) * 32;
        float u[8];
#pragma unroll
        for (int e = 0; e < 8; e++) {
            int oc = (e & 2) ? oc1 : oc0;
            int klx = kl + ((e >> 2) ? 8 : 0) + (e & 1);
            u[e] = w3[oc * 576 + (icb + klx) * 9 + tap];
        }
        uint4 H, L;
        pack_frag(u, H, L);
        g_w3p_h[i] = H; g_w3p_l[i] = L;
    }
}

// ---------------- conv1: 3->32, 7x7 s4 p3, 224 -> 56, K=160 -----------------
__global__ void __launch_bounds__(256) conv1_mma(
        const float* __restrict__ x,
        const float* __restrict__ bg, const float* __restrict__ bb,
        const float* __restrict__ bm, const float* __restrict__ bv,
        const float* __restrict__ cb) {
    __shared__ __align__(16) uint4 sAh[2][8 * 18], sAl[2][8 * 18];
    __shared__ __align__(8) uint2 sBh[2][8 * 132], sBl[2][8 * 132];
    const int tid = threadIdx.x;
    const int b = blockIdx.y;
    const int pxt = blockIdx.x * 128;
    const int wid = tid >> 5, lane = tid & 31, gid = lane >> 2, tig = lane & 3;
    const int otile = wid & 1;
    const int pxw = (wid >> 1) * 32;

    float acc[4][4];
#pragma unroll
    for (int n = 0; n < 4; n++)
#pragma unroll
        for (int j = 0; j < 4; j++) acc[n][j] = 0.f;

    const int pxl = tid & 127;
    const int ksl = tid >> 7;
    const int pxg = pxt + pxl;
    const int oh = pxg / 56, ow = pxg % 56;
    const int ihb = oh * 4 - 3, iwb = ow * 4 - 3;
    const float* xb = x + (size_t)b * 3 * 50176;

    float rv0[8], rv1[8];
    auto loadk = [&](int k) -> float {
        if (k >= 147) return 0.f;
        int tap = k / 3, ic = k - tap * 3;
        int kh = tap / 7, kw = tap - kh * 7;
        int ih = ihb + kh, iw = iwb + kw;
        return ((unsigned)ih < 224u && (unsigned)iw < 224u)
                   ? __ldg(xb + ic * 50176 + ih * 224 + iw) : 0.f;
    };
    auto ldgB = [&](int c) {
#pragma unroll
        for (int j = 0; j < 8; j++) {
            int k0 = c * 32 + ksl * 16 + 2 * j;
            rv0[j] = loadk(k0);
            rv1[j] = loadk(k0 + 1);
        }
    };
    auto cpA = [&](int c, int buf) {
        if (tid < 128) {
            cpa16(&sAh[buf][(tid >> 4) * 18 + (tid & 15)], g_w1p_h + c * 128 + tid);
        } else {
            int e = tid - 128;
            cpa16(&sAl[buf][(e >> 4) * 18 + (e & 15)], g_w1p_l + c * 128 + e);
        }
    };

    ldgB(0);
    cpA(0, 0);
    CP_COMMIT();

    for (int c = 0; c < 5; c++) {
        const int buf = c & 1;
        CP_WAIT0();
#pragma unroll
        for (int j = 0; j < 8; j++) {
            unsigned short h0, l0, h1, l1;
            fsplit(rv0[j], h0, l0);
            fsplit(rv1[j], h1, l1);
            unsigned int hi2 = (unsigned)h0 | ((unsigned)h1 << 16);
            unsigned int lo2 = (unsigned)l0 | ((unsigned)l1 << 16);
            int row = ksl * 4 + (j & 3), reg = j >> 2;
            ((unsigned int*)&sBh[buf][row * 132 + pxl])[reg] = hi2;
            ((unsigned int*)&sBl[buf][row * 132 + pxl])[reg] = lo2;
        }
        __syncthreads();
        if (c < 4) {
            ldgB(c + 1);
            cpA(c + 1, buf ^ 1);
            CP_COMMIT();
        }
        const int tb = otile * 8 + gid;
#pragma unroll
        for (int step = 0; step < 2; step++) {
            int rb = step * 4 + tig;
            uint4 aH = sAh[buf][rb * 18 + tb];
            uint4 aL = sAl[buf][rb * 18 + tb];
#pragma unroll
            for (int nf = 0; nf < 4; nf++) {
                int col = pxw + nf * 8 + gid;
                uint2 bH = sBh[buf][rb * 132 + col];
                uint2 bL = sBl[buf][rb * 132 + col];
                MMA3F(acc[nf], aH, aL, bH, bL);
            }
        }
    }
    int r0 = otile * 16 + gid, r1 = r0 + 8;
    float s0 = bg[r0] * rsqrtf(bv[r0] + 1e-5f);
    float h0 = (cb[r0] - bm[r0]) * s0 + bb[r0];
    float s1 = bg[r1] * rsqrtf(bv[r1] + 1e-5f);
    float h1 = (cb[r1] - bm[r1]) * s1 + bb[r1];
    size_t o0 = ((size_t)b * 32 + r0) * 3136;
    size_t o1 = ((size_t)b * 32 + r1) * 3136;
#pragma unroll
    for (int nf = 0; nf < 4; nf++) {
        int col = pxt + pxw + nf * 8 + 2 * tig;
        if (col < 3136) {
            uint2 p0, p1;
            p0.x = packsplit(fmaxf(acc[nf][0] * s0 + h0, 0.f));
            p0.y = packsplit(fmaxf(acc[nf][1] * s0 + h0, 0.f));
            p1.x = packsplit(fmaxf(acc[nf][2] * s1 + h1, 0.f));
            p1.y = packsplit(fmaxf(acc[nf][3] * s1 + h1, 0.f));
            *reinterpret_cast<uint2*>(g_a1p + o0 + col) = p0;
            *reinterpret_cast<uint2*>(g_a1p + o1 + col) = p1;
        }
    }
}

// ---------------- conv2: 32->64, 3x3 s2 p1, 56 -> 28 ------------------------
__global__ void __launch_bounds__(256) conv2_mma(
        const float* __restrict__ bg, const float* __restrict__ bb,
        const float* __restrict__ bm, const float* __restrict__ bv,
        const float* __restrict__ cb) {
    __shared__ __align__(16) uint4 sAh[2][8 * 34], sAl[2][8 * 34];
    __shared__ __align__(8) uint2 sBh[2][8 * 68], sBl[2][8 * 68];
    const int tid = threadIdx.x;
    const int b = blockIdx.y;
    const int pxt = blockIdx.x * 64;
    const int wid = tid >> 5, lane = tid & 31, gid = lane >> 2, tig = lane & 3;
    const int otile = wid & 3;
    const int pxw = (wid >> 2) * 32;

    float acc[4][4];
#pragma unroll
    for (int n = 0; n < 4; n++)
#pragma unroll
        for (int j = 0; j < 4; j++) acc[n][j] = 0.f;

    const int pxl = tid & 63;
    const int ksl = tid >> 6;
    const int pxg = pxt + pxl;
    const int oh = pxg / 28, ow = pxg % 28;
    const int ihb = oh * 2 - 1, iwb = ow * 2 - 1;
    const unsigned* a1b = g_a1p + (size_t)b * 32 * 3136;

    unsigned rp0[4], rp1[4];
    auto ldgB = [&](int c) {
        int kh = (c * 11) >> 5;
        int kw = c - kh * 3;
        int ih = ihb + kh, iw = iwb + kw;
        bool okc = (unsigned)ih < 56u && (unsigned)iw < 56u;
        const unsigned* src = a1b + ih * 56 + iw;
#pragma unroll
        for (int j = 0; j < 4; j++) {
            int k0 = ksl * 8 + 2 * j;
            rp0[j] = okc ? __ldg(src + (size_t)k0 * 3136) : 0u;
            rp1[j] = okc ? __ldg(src + (size_t)(k0 + 1) * 3136) : 0u;
        }
    };
    auto cpA = [&](int c, int buf) {
        cpa16(&sAh[buf][(tid >> 5) * 34 + (tid & 31)], g_w2p_h + c * 256 + tid);
        cpa16(&sAl[buf][(tid >> 5) * 34 + (tid & 31)], g_w2p_l + c * 256 + tid);
    };

    ldgB(0);
    cpA(0, 0);
    CP_COMMIT();

    for (int c = 0; c < 9; c++) {
        const int buf = c & 1;
        CP_WAIT0();
#pragma unroll
        for (int j = 0; j < 4; j++) {
            unsigned int hi2 = __byte_perm(rp0[j], rp1[j], 0x5410);
            unsigned int lo2 = __byte_perm(rp0[j], rp1[j], 0x7632);
            int row = (ksl >> 1) * 4 + j, reg = ksl & 1;
            ((unsigned int*)&sBh[buf][row * 68 + pxl])[reg] = hi2;
            ((unsigned int*)&sBl[buf][row * 68 + pxl])[reg] = lo2;
        }
        __syncthreads();
        if (c < 8) {
            ldgB(c + 1);
            cpA(c + 1, buf ^ 1);
            CP_COMMIT();
        }
        const int tb = otile * 8 + gid;
#pragma unroll
        for (int step = 0; step < 2; step++) {
            int rb = step * 4 + tig;
            uint4 aH = sAh[buf][rb * 34 + tb];
            uint4 aL = sAl[buf][rb * 34 + tb];
#pragma unroll
            for (int nf = 0; nf < 4; nf++) {
                int col = pxw + nf * 8 + gid;
                uint2 bH = sBh[buf][rb * 68 + col];
                uint2 bL = sBl[buf][rb * 68 + col];
                MMA3F(acc[nf], aH, aL, bH, bL);
            }
        }
    }
    int r0 = otile * 16 + gid, r1 = r0 + 8;
    float s0 = bg[r0] * rsqrtf(bv[r0] + 1e-5f);
    float h0 = (cb[r0] - bm[r0]) * s0 + bb[r0];
    float s1 = bg[r1] * rsqrtf(bv[r1] + 1e-5f);
    float h1 = (cb[r1] - bm[r1]) * s1 + bb[r1];
    size_t o0 = ((size_t)b * 64 + r0) * 784;
    size_t o1 = ((size_t)b * 64 + r1) * 784;
#pragma unroll
    for (int nf = 0; nf < 4; nf++) {
        int col = pxt + pxw + nf * 8 + 2 * tig;
        if (col < 784) {
            uint2 p0, p1;
            p0.x = packsplit(fmaxf(acc[nf][0] * s0 + h0, 0.f));
            p0.y = packsplit(fmaxf(acc[nf][1] * s0 + h0, 0.f));
            p1.x = packsplit(fmaxf(acc[nf][2] * s1 + h1, 0.f));
            p1.y = packsplit(fmaxf(acc[nf][3] * s1 + h1, 0.f));
            *reinterpret_cast<uint2*>(g_a2p + o0 + col) = p0;
            *reinterpret_cast<uint2*>(g_a2p + o1 + col) = p1;
        }
    }
}

// ---------------- conv3: 64->128, 3x3 s2 p1, 28 -> 14 (128 oc, 1 bar) -------
__global__ void __launch_bounds__(256) conv3_mma(
        const float* __restrict__ bg, const float* __restrict__ bb,
        const float* __restrict__ bm, const float* __restrict__ bv,
        const float* __restrict__ cb) {
    extern __shared__ __align__(16) unsigned char dsm[];
    uint4* sAh = (uint4*)dsm;                    // [2][8*66]
    uint4* sAl = sAh + 2 * 528;                  // [2][8*66]
    uint2* sBh = (uint2*)(sAl + 2 * 528);        // [2][8*68]
    uint2* sBl = sBh + 2 * 544;                  // [2][8*68]
    const int tid = threadIdx.x;
    const int b = blockIdx.y;
    const int pxt = blockIdx.x * 64;
    const int wid = tid >> 5, lane = tid & 31, gid = lane >> 2, tig = lane & 3;

    float acc[8][4];
#pragma unroll
    for (int n = 0; n < 8; n++)
#pragma unroll
        for (int j = 0; j < 4; j++) acc[n][j] = 0.f;

    const int pxl = tid & 63;
    const int ksl = tid >> 6;
    const int pxg = pxt + pxl;
    const int oh = pxg / 14, ow = pxg % 14;
    const int ihb = oh * 2 - 1, iwb = ow * 2 - 1;
    const unsigned* a2b = g_a2p + (size_t)b * 64 * 784;

    unsigned rp0[4], rp1[4];
    auto ldgB = [&](int c) {
        int t = c >> 1;
        int kh = (t * 11) >> 5;
        int kw = t - kh * 3;
        int ih = ihb + kh, iw = iwb + kw;
        bool okc = (unsigned)ih < 28u && (unsigned)iw < 28u;
        const unsigned* src = a2b + (c & 1) * 32 * 784 + ih * 28 + iw;
#pragma unroll
        for (int j = 0; j < 4; j++) {
            int k0 = ksl * 8 + 2 * j;
            rp0[j] = okc ? __ldg(src + (size_t)k0 * 784) : 0u;
            rp1[j] = okc ? __ldg(src + (size_t)(k0 + 1) * 784) : 0u;
        }
    };
    auto cpA = [&](int c, int buf) {
#pragma unroll
        for (int i = 0; i < 2; i++) {
            int e = tid + i * 256;
            cpa16(&sAh[buf * 528 + (e >> 6) * 66 + (e & 63)], g_w3p_h + c * 512 + e);
            cpa16(&sAl[buf * 528 + (e >> 6) * 66 + (e & 63)], g_w3p_l + c * 512 + e);
        }
    };

    ldgB(0);
    cpA(0, 0);
    CP_COMMIT();

    for (int c = 0; c < 18; c++) {
        const int buf = c & 1;
#pragma unroll
        for (int j = 0; j < 4; j++) {
            unsigned int hi2 = __byte_perm(rp0[j], rp1[j], 0x5410);
            unsigned int lo2 = __byte_perm(rp0[j], rp1[j], 0x7632);
            int row = (ksl >> 1) * 4 + j, reg = ksl & 1;
            ((unsigned int*)&sBh[buf * 544 + row * 68 + pxl])[reg] = hi2;
            ((unsigned int*)&sBl[buf * 544 + row * 68 + pxl])[reg] = lo2;
        }
        CP_WAIT0();
        __syncthreads();
        if (c < 17) {
            ldgB(c + 1);
            cpA(c + 1, buf ^ 1);
            CP_COMMIT();
        }
        const int tb = wid * 8 + gid;
#pragma unroll
        for (int step = 0; step < 2; step++) {
            int rb = step * 4 + tig;
            uint4 aH = sAh[buf * 528 + rb * 66 + tb];
            uint4 aL = sAl[buf * 528 + rb * 66 + tb];
#pragma unroll
            for (int nf = 0; nf < 8; nf++) {
                int col = nf * 8 + gid;
                uint2 bH = sBh[buf * 544 + rb * 68 + col];
                uint2 bL = sBl[buf * 544 + rb * 68 + col];
                MMA3F(acc[nf], aH, aL, bH, bL);
            }
        }
    }
    int r0 = wid * 16 + gid, r1 = r0 + 8;
    float s0 = bg[r0] * rsqrtf(bv[r0] + 1e-5f);
    float h0 = (cb[r0] - bm[r0]) * s0 + bb[r0];
    float s1 = bg[r1] * rsqrtf(bv[r1] + 1e-5f);
    float h1 = (cb[r1] - bm[r1]) * s1 + bb[r1];
    float* o0 = g_a3 + ((size_t)b * 128 + r0) * 196;
    float* o1 = g_a3 + ((size_t)b * 128 + r1) * 196;
#pragma unroll
    for (int nf = 0; nf < 8; nf++) {
        int col = pxt + nf * 8 + 2 * tig;
        if (col < 196) {
            float2 v0 = make_float2(fmaxf(acc[nf][0] * s0 + h0, 0.f),
                                    fmaxf(acc[nf][1] * s0 + h0, 0.f));
            float2 v1 = make_float2(fmaxf(acc[nf][2] * s1 + h1, 0.f),
                                    fmaxf(acc[nf][3] * s1 + h1, 0.f));
            *reinterpret_cast<float2*>(o0 + col) = v0;
            *reinterpret_cast<float2*>(o1 + col) = v1;
        }
    }
}

// ---------------- adaptive avgpool (2,2): 14x14 -> 2x2 ----------------------
__global__ void pool_kernel() {
    int idx = blockIdx.x * 256 + threadIdx.x;
    if (idx >= 128 * 512) return;
    int b = idx >> 9;
    int r = idx & 511;
    int c = r >> 2;
    int ph = (r >> 1) & 1;
    int pw = r & 1;
    const float* src = g_a3 + (((size_t)b * 128 + c) * 14 + ph * 7) * 14 + pw * 7;
    float s = 0.f;
#pragma unroll
    for (int h = 0; h < 7; h++)
#pragma unroll
        for (int w = 0; w < 7; w++) s += src[h * 14 + w];
    g_feat[idx] = s * (1.f / 49.f);
}

// ---------------- head: linear->tanh, quantum circuit, MLP ------------------
__global__ void head_kernel(const float* __restrict__ pre_w, const float* __restrict__ pre_b,
                            const float* __restrict__ qw,
                            const float* __restrict__ pw1, const float* __restrict__ pb1,
                            const float* __restrict__ pw2, const float* __restrict__ pb2,
                            float* __restrict__ out) {
    __shared__ float f_s[512];
    __shared__ float ang_s[4], q_s[4], h1_s[64];
    const int tid = threadIdx.x;
    const int b = blockIdx.x;

    for (int i = tid; i < 512; i += 128) f_s[i] = g_feat[b * 512 + i];
    __syncthreads();

    int wid = tid >> 5, lane = tid & 31;
    {
        float partial = 0.f;
        const float* wr = pre_w + wid * 512;
        for (int k = lane; k < 512; k += 32) partial += f_s[k] * wr[k];
#pragma unroll
        for (int o = 16; o > 0; o >>= 1) partial += __shfl_down_sync(0xffffffffu, partial, o);
        if (lane == 0) ang_s[wid] = tanhf(partial + pre_b[wid]) * 3.14159265358979323846f;
    }
    __syncthreads();

    if (tid == 0) {
        float sr[16], si[16];
        float cq[4], sq[4];
#pragma unroll
        for (int q = 0; q < 4; q++) {
            cq[q] = cosf(0.5f * ang_s[q]);
            sq[q] = sinf(0.5f * ang_s[q]);
        }
#pragma unroll
        for (int i = 0; i < 16; i++) {
            float vv = 1.f;
#pragma unroll
            for (int q = 0; q < 4; q++) vv *= ((i >> (3 - q)) & 1) ? sq[q] : cq[q];
            sr[i] = vv;
            si[i] = 0.f;
        }
        for (int l = 0; l < 2; l++) {
            for (int q = 0; q < 4; q++) {
                const int mk = 1 << (3 - q);
                const float* qwp = qw + (l * 4 + q) * 3;
                float c, s;
                c = cosf(0.5f * qwp[0]); s = sinf(0.5f * qwp[0]);
                for (int i = 0; i < 16; i++)
                    if (!(i & mk)) {
                        int j = i | mk;
                        float r0 = sr[i], i0 = si[i], r1 = sr[j], i1 = si[j];
                        sr[i] = c * r0 + s * i1;  si[i] = c * i0 - s * r1;
                        sr[j] = c * r1 + s * i0;  si[j] = c * i1 - s * r0;
                    }
                c = cosf(0.5f * qwp[1]); s = sinf(0.5f * qwp[1]);
                for (int i = 0; i < 16; i++)
                    if (!(i & mk)) {
                        int j = i | mk;
                        float r0 = sr[i], i0 = si[i], r1 = sr[j], i1 = si[j];
                        sr[i] = c * r0 - s * r1;  si[i] = c * i0 - s * i1;
                        sr[j] = s * r0 + c * r1;  si[j] = s * i0 + c * i1;
                    }
                c = cosf(0.5f * qwp[2]); s = sinf(0.5f * qwp[2]);
                for (int i = 0; i < 16; i++) {
                    float r = sr[i], im = si[i];
                    if (i & mk) { sr[i] = c * r - s * im; si[i] = c * im + s * r; }
                    else        { sr[i] = c * r + s * im; si[i] = c * im - s * r; }
                }
            }
            for (int e = 0; e < 4; e++) {
                int cm = 1 << (3 - e);
                int tm = 1 << (3 - ((e + 1) & 3));
                for (int i = 0; i < 16; i++)
                    if ((i & cm) && !(i & tm)) {
                        int j = i | tm;
                        float t = sr[i]; sr[i] = sr[j]; sr[j] = t;
                        t = si[i]; si[i] = si[j]; si[j] = t;
                    }
            }
        }
        for (int q = 0; q < 4; q++) {
            float z = 0.f;
            for (int i = 0; i < 16; i++) {
                float pp = sr[i] * sr[i] + si[i] * si[i];
                z += ((i >> (3 - q)) & 1) ? -pp : pp;
            }
            q_s[q] = z;
        }
    }
    __syncthreads();

    if (tid < 64) {
        float h = pb1[tid];
#pragma unroll
        for (int j = 0; j < 4; j++) h += q_s[j] * pw1[tid * 4 + j];
        h1_s[tid] = fmaxf(h, 0.f);
    }
    __syncthreads();

    if (tid < 5) {
        float o = pb2[tid];
        for (int k = 0; k < 64; k++) o += h1_s[k] * pw2[tid * 64 + k];
        out[b * 5 + tid] = o;
    }
}

// ---------------- launch ----------------------------------------------------
extern "C" void kernel_launch(void* const* d_in, const int* in_sizes, int n_in,
                              void* d_out, int out_size) {
    const float* x    = (const float*)d_in[0];
    const float* c1w  = (const float*)d_in[1];
    const float* c1b  = (const float*)d_in[2];
    const float* bn1g = (const float*)d_in[3];
    const float* bn1b = (const float*)d_in[4];
    const float* bn1m = (const float*)d_in[5];
    const float* bn1v = (const float*)d_in[6];
    const float* c2w  = (const float*)d_in[7];
    const float* c2b  = (const float*)d_in[8];
    const float* bn2g = (const float*)d_in[9];
    const float* bn2b = (const float*)d_in[10];
    const float* bn2m = (const float*)d_in[11];
    const float* bn2v = (const float*)d_in[12];
    const float* c3w  = (const float*)d_in[13];
    const float* c3b  = (const float*)d_in[14];
    const float* bn3g = (const float*)d_in[15];
    const float* bn3b = (const float*)d_in[16];
    const float* bn3m = (const float*)d_in[17];
    const float* bn3v = (const float*)d_in[18];
    const float* pre_w = (const float*)d_in[19];
    const float* pre_b = (const float*)d_in[20];
    const float* qw    = (const float*)d_in[21];
    const float* pw1   = (const float*)d_in[22];
    const float* pb1   = (const float*)d_in[23];
    const float* pw2   = (const float*)d_in[24];
    const float* pb2   = (const float*)d_in[25];
    float* out = (float*)d_out;

    const int conv3_smem = 2 * 528 * 16 * 2 + 2 * 544 * 8 * 2;  // 51200
    cudaFuncSetAttribute(conv3_mma, cudaFuncAttributeMaxDynamicSharedMemorySize,
                         conv3_smem);

    prep_w<<<36, 256>>>(c1w, c2w, c3w);
    conv1_mma<<<dim3(25, 128), 256>>>(x, bn1g, bn1b, bn1m, bn1v, c1b);
    conv2_mma<<<dim3(13, 128), 256>>>(bn2g, bn2b, bn2m, bn2v, c2b);
    conv3_mma<<<dim3(4, 128), 256, conv3_smem>>>(bn3g, bn3b, bn3m, bn3v, c3b);
    pool_kernel<<<256, 256>>>();
    head_kernel<<<128, 128>>>(pre_w, pre_b, qw, pw1, pb1, pw2, pb2, out);
}

// round 15
// speedup vs baseline: 1.0228x; 1.0228x over previous
#include <cuda_runtime.h>
#include <cuda_fp16.h>
#include <math.h>

// ---------------- intermediate buffers (device globals) ---------------------
__device__ unsigned int g_a1p[128 * 32 * 56 * 56];  // conv1 out, packed {hi,lo}
__device__ unsigned int g_a2p[128 * 64 * 28 * 28];  // conv2 out, packed {hi,lo}
__device__ float g_a3[128 * 128 * 14 * 14];         // conv3 out
__device__ float g_feat[128 * 512];                 // pooled features

// packed fp16 weight fragments (hi and lo planes)
// conv1: K ic-fastest (k = 3*tap + ic), padded 147 -> 160 (5 chunks)
__device__ uint4 g_w1p_h[5 * 8 * 16],  g_w1p_l[5 * 8 * 16];
__device__ uint4 g_w2p_h[9 * 8 * 32],  g_w2p_l[9 * 8 * 32];
__device__ uint4 g_w3p_h[18 * 8 * 64], g_w3p_l[18 * 8 * 64];

// ---------------- helpers ---------------------------------------------------
__device__ __forceinline__ void fsplit(float v, unsigned short& h, unsigned short& l) {
    __half hh = __float2half_rn(v);
    __half ll = __float2half_rn(v - __half2float(hh));
    h = __half_as_ushort(hh);
    l = __half_as_ushort(ll);
}
__device__ __forceinline__ unsigned int packsplit(float v) {
    unsigned short h, l;
    fsplit(v, h, l);
    return (unsigned)h | ((unsigned)l << 16);
}

#define MMAF(d, a, b0, b1)                                                      \
    asm volatile(                                                               \
        "mma.sync.aligned.m16n8k16.row.col.f32.f16.f16.f32 "                    \
        "{%0,%1,%2,%3}, {%4,%5,%6,%7}, {%8,%9}, {%0,%1,%2,%3};"                 \
        : "+f"(d[0]), "+f"(d[1]), "+f"(d[2]), "+f"(d[3])                        \
        : "r"(a.x), "r"(a.y), "r"(a.z), "r"(a.w), "r"(b0), "r"(b1))

#define MMA3F(acc, aH, aL, bH, bL)                                              \
    do {                                                                        \
        MMAF(acc, aH, bH.x, bH.y);                                              \
        MMAF(acc, aH, bL.x, bL.y);                                              \
        MMAF(acc, aL, bH.x, bH.y);                                              \
    } while (0)

__device__ __forceinline__ void cpa16(void* sdst, const void* gsrc) {
    unsigned s = (unsigned)__cvta_generic_to_shared(sdst);
    asm volatile("cp.async.cg.shared.global [%0], [%1], 16;"
                 :: "r"(s), "l"(gsrc) : "memory");
}
#define CP_COMMIT() asm volatile("cp.async.commit_group;" ::: "memory")
#define CP_WAIT0()  asm volatile("cp.async.wait_group 0;" ::: "memory")

// ---------------- weight prep ------------------------------------------------
__device__ __forceinline__ void pack_frag(const float* v, uint4& H, uint4& L) {
    unsigned short h[8], l[8];
#pragma unroll
    for (int i = 0; i < 8; i++) fsplit(v[i], h[i], l[i]);
    H.x = h[0] | (h[1] << 16); H.y = h[2] | (h[3] << 16);
    H.z = h[4] | (h[5] << 16); H.w = h[6] | (h[7] << 16);
    L.x = l[0] | (l[1] << 16); L.y = l[2] | (l[3] << 16);
    L.z = l[4] | (l[5] << 16); L.w = l[6] | (l[7] << 16);
}

__global__ void prep_w(const float* __restrict__ w1, const float* __restrict__ w2,
                       const float* __restrict__ w3) {
    int i = blockIdx.x * 256 + threadIdx.x;
    if (i < 5 * 8 * 16) {
        int chunk = i >> 7, row = (i >> 4) & 7, t = i & 15;
        int tile = t >> 3, gid = t & 7;
        int step = row >> 2, tig = row & 3;
        int oc0 = tile * 16 + gid, oc1 = oc0 + 8;
        int kl = step * 16 + tig * 2;
        float u[8];
#pragma unroll
        for (int e = 0; e < 8; e++) {
            int oc = (e & 2) ? oc1 : oc0;
            int klx = kl + ((e >> 2) ? 8 : 0) + (e & 1);
            int k = chunk * 32 + klx;  // k = 3*tap + ic
            float v = 0.f;
            if (k < 147) {
                int tap = k / 3, ic = k - tap * 3;
                int kh = tap / 7, kw = tap - kh * 7;
                v = w1[oc * 147 + ic * 49 + kh * 7 + kw];
            }
            u[e] = v;
        }
        uint4 H, L;
        pack_frag(u, H, L);
        g_w1p_h[i] = H; g_w1p_l[i] = L;
    }
    if (i < 9 * 8 * 32) {
        int chunk = i >> 8, r = i & 255;
        int row = r >> 5, t = r & 31;
        int tile = t >> 3, gid = t & 7;
        int step = row >> 2, tig = row & 3;
        int oc0 = tile * 16 + gid, oc1 = oc0 + 8;
        int kl = step * 16 + tig * 2;
        float u[8];
#pragma unroll
        for (int e = 0; e < 8; e++) {
            int oc = (e & 2) ? oc1 : oc0;
            int klx = kl + ((e >> 2) ? 8 : 0) + (e & 1);
            u[e] = w2[oc * 288 + klx * 9 + chunk];
        }
        uint4 H, L;
        pack_frag(u, H, L);
        g_w2p_h[i] = H; g_w2p_l[i] = L;
    }
    if (i < 18 * 8 * 64) {
        int chunk = i >> 9, r = i & 511;
        int row = r >> 6, t = r & 63;
        int tile = t >> 3, gid = t & 7;
        int step = row >> 2, tig = row & 3;
        int oc0 = tile * 16 + gid, oc1 = oc0 + 8;
        int kl = step * 16 + tig * 2;
        int tap = chunk >> 1, icb = (chunk & 1) * 32;
        float u[8];
#pragma unroll
        for (int e = 0; e < 8; e++) {
            int oc = (e & 2) ? oc1 : oc0;
            int klx = kl + ((e >> 2) ? 8 : 0) + (e & 1);
            u[e] = w3[oc * 576 + (icb + klx) * 9 + tap];
        }
        uint4 H, L;
        pack_frag(u, H, L);
        g_w3p_h[i] = H; g_w3p_l[i] = L;
    }
}

// ---------------- conv1: 3->32, 7x7 s4 p3, 224 -> 56, K=160 -----------------
__global__ void __launch_bounds__(256) conv1_mma(
        const float* __restrict__ x,
        const float* __restrict__ bg, const float* __restrict__ bb,
        const float* __restrict__ bm, const float* __restrict__ bv,
        const float* __restrict__ cb) {
    __shared__ __align__(16) uint4 sAh[2][8 * 18], sAl[2][8 * 18];
    __shared__ __align__(8) uint2 sBh[2][8 * 132], sBl[2][8 * 132];
    const int tid = threadIdx.x;
    const int b = blockIdx.y;
    const int pxt = blockIdx.x * 128;
    const int wid = tid >> 5, lane = tid & 31, gid = lane >> 2, tig = lane & 3;
    const int otile = wid & 1;
    const int pxw = (wid >> 1) * 32;

    float acc[4][4];
#pragma unroll
    for (int n = 0; n < 4; n++)
#pragma unroll
        for (int j = 0; j < 4; j++) acc[n][j] = 0.f;

    const int pxl = tid & 127;
    const int ksl = tid >> 7;
    const int pxg = pxt + pxl;
    const int oh = pxg / 56, ow = pxg % 56;
    const int ihb = oh * 4 - 3, iwb = ow * 4 - 3;
    // base pointer at (ic=0, ih=ihb, iw=iwb); per-k offset = ic*50176 + kh*224 + kw
    const float* xbase = x + (size_t)b * 3 * 50176 + ihb * 224 + iwb;

    float rv0[8], rv1[8];
    auto ldgB = [&](int c) {
        const int kbase = c * 32 + ksl * 16;
#pragma unroll
        for (int j = 0; j < 8; j++) {
            // two consecutive k; decode with constant-divisor magic (compiler)
            int ka = kbase + 2 * j;
            int kb = ka + 1;
            int tapa = ka / 3, ica = ka - tapa * 3;
            int kha = tapa / 7, kwa = tapa - kha * 7;
            int tapb = kb / 3, icb2 = kb - tapb * 3;
            int khb = tapb / 7, kwb = tapb - khb * 7;
            bool oka = (ka < 147) && (unsigned)(ihb + kha) < 224u &&
                       (unsigned)(iwb + kwa) < 224u;
            bool okb = (kb < 147) && (unsigned)(ihb + khb) < 224u &&
                       (unsigned)(iwb + kwb) < 224u;
            rv0[j] = oka ? __ldg(xbase + ica * 50176 + kha * 224 + kwa) : 0.f;
            rv1[j] = okb ? __ldg(xbase + icb2 * 50176 + khb * 224 + kwb) : 0.f;
        }
    };
    auto cpA = [&](int c, int buf) {
        if (tid < 128) {
            cpa16(&sAh[buf][(tid >> 4) * 18 + (tid & 15)], g_w1p_h + c * 128 + tid);
        } else {
            int e = tid - 128;
            cpa16(&sAl[buf][(e >> 4) * 18 + (e & 15)], g_w1p_l + c * 128 + e);
        }
    };

    ldgB(0);
    cpA(0, 0);
    CP_COMMIT();

    for (int c = 0; c < 5; c++) {
        const int buf = c & 1;
        CP_WAIT0();
#pragma unroll
        for (int j = 0; j < 8; j++) {
            unsigned short h0, l0, h1, l1;
            fsplit(rv0[j], h0, l0);
            fsplit(rv1[j], h1, l1);
            unsigned int hi2 = (unsigned)h0 | ((unsigned)h1 << 16);
            unsigned int lo2 = (unsigned)l0 | ((unsigned)l1 << 16);
            int row = ksl * 4 + (j & 3), reg = j >> 2;
            ((unsigned int*)&sBh[buf][row * 132 + pxl])[reg] = hi2;
            ((unsigned int*)&sBl[buf][row * 132 + pxl])[reg] = lo2;
        }
        __syncthreads();
        if (c < 4) {
            ldgB(c + 1);
            cpA(c + 1, buf ^ 1);
            CP_COMMIT();
        }
        const int tb = otile * 8 + gid;
#pragma unroll
        for (int step = 0; step < 2; step++) {
            int rb = step * 4 + tig;
            uint4 aH = sAh[buf][rb * 18 + tb];
            uint4 aL = sAl[buf][rb * 18 + tb];
#pragma unroll
            for (int nf = 0; nf < 4; nf++) {
                int col = pxw + nf * 8 + gid;
                uint2 bH = sBh[buf][rb * 132 + col];
                uint2 bL = sBl[buf][rb * 132 + col];
                MMA3F(acc[nf], aH, aL, bH, bL);
            }
        }
    }
    int r0 = otile * 16 + gid, r1 = r0 + 8;
    float s0 = bg[r0] * rsqrtf(bv[r0] + 1e-5f);
    float h0 = (cb[r0] - bm[r0]) * s0 + bb[r0];
    float s1 = bg[r1] * rsqrtf(bv[r1] + 1e-5f);
    float h1 = (cb[r1] - bm[r1]) * s1 + bb[r1];
    size_t o0 = ((size_t)b * 32 + r0) * 3136;
    size_t o1 = ((size_t)b * 32 + r1) * 3136;
#pragma unroll
    for (int nf = 0; nf < 4; nf++) {
        int col = pxt + pxw + nf * 8 + 2 * tig;
        if (col < 3136) {
            uint2 p0, p1;
            p0.x = packsplit(fmaxf(acc[nf][0] * s0 + h0, 0.f));
            p0.y = packsplit(fmaxf(acc[nf][1] * s0 + h0, 0.f));
            p1.x = packsplit(fmaxf(acc[nf][2] * s1 + h1, 0.f));
            p1.y = packsplit(fmaxf(acc[nf][3] * s1 + h1, 0.f));
            *reinterpret_cast<uint2*>(g_a1p + o0 + col) = p0;
            *reinterpret_cast<uint2*>(g_a1p + o1 + col) = p1;
        }
    }
}

// ---------------- conv2: 32->64, 3x3 s2 p1, 56 -> 28 (R13 exact) ------------
__global__ void __launch_bounds__(256) conv2_mma(
        const float* __restrict__ bg, const float* __restrict__ bb,
        const float* __restrict__ bm, const float* __restrict__ bv,
        const float* __restrict__ cb) {
    __shared__ __align__(16) uint4 sAh[2][8 * 34], sAl[2][8 * 34];
    __shared__ __align__(8) uint2 sBh[2][8 * 68], sBl[2][8 * 68];
    const int tid = threadIdx.x;
    const int b = blockIdx.y;
    const int pxt = blockIdx.x * 64;
    const int wid = tid >> 5, lane = tid & 31, gid = lane >> 2, tig = lane & 3;
    const int otile = wid & 3;
    const int pxw = (wid >> 2) * 32;

    float acc[4][4];
#pragma unroll
    for (int n = 0; n < 4; n++)
#pragma unroll
        for (int j = 0; j < 4; j++) acc[n][j] = 0.f;

    const int pxl = tid & 63;
    const int ksl = tid >> 6;
    const int pxg = pxt + pxl;
    const int oh = pxg / 28, ow = pxg % 28;
    const int ihb = oh * 2 - 1, iwb = ow * 2 - 1;
    const unsigned* a1b = g_a1p + (size_t)b * 32 * 3136;

    unsigned rp0[4], rp1[4];
    auto ldgB = [&](int c) {
        int kh = (c * 11) >> 5;
        int kw = c - kh * 3;
        int ih = ihb + kh, iw = iwb + kw;
        bool okc = (unsigned)ih < 56u && (unsigned)iw < 56u;
        const unsigned* src = a1b + ih * 56 + iw;
#pragma unroll
        for (int j = 0; j < 4; j++) {
            int k0 = ksl * 8 + 2 * j;
            rp0[j] = okc ? __ldg(src + (size_t)k0 * 3136) : 0u;
            rp1[j] = okc ? __ldg(src + (size_t)(k0 + 1) * 3136) : 0u;
        }
    };
    auto cpA = [&](int c, int buf) {
        cpa16(&sAh[buf][(tid >> 5) * 34 + (tid & 31)], g_w2p_h + c * 256 + tid);
        cpa16(&sAl[buf][(tid >> 5) * 34 + (tid & 31)], g_w2p_l + c * 256 + tid);
    };

    ldgB(0);
    cpA(0, 0);
    CP_COMMIT();

    for (int c = 0; c < 9; c++) {
        const int buf = c & 1;
        CP_WAIT0();
#pragma unroll
        for (int j = 0; j < 4; j++) {
            unsigned int hi2 = __byte_perm(rp0[j], rp1[j], 0x5410);
            unsigned int lo2 = __byte_perm(rp0[j], rp1[j], 0x7632);
            int row = (ksl >> 1) * 4 + j, reg = ksl & 1;
            ((unsigned int*)&sBh[buf][row * 68 + pxl])[reg] = hi2;
            ((unsigned int*)&sBl[buf][row * 68 + pxl])[reg] = lo2;
        }
        __syncthreads();
        if (c < 8) {
            ldgB(c + 1);
            cpA(c + 1, buf ^ 1);
            CP_COMMIT();
        }
        const int tb = otile * 8 + gid;
#pragma unroll
        for (int step = 0; step < 2; step++) {
            int rb = step * 4 + tig;
            uint4 aH = sAh[buf][rb * 34 + tb];
            uint4 aL = sAl[buf][rb * 34 + tb];
#pragma unroll
            for (int nf = 0; nf < 4; nf++) {
                int col = pxw + nf * 8 + gid;
                uint2 bH = sBh[buf][rb * 68 + col];
                uint2 bL = sBl[buf][rb * 68 + col];
                MMA3F(acc[nf], aH, aL, bH, bL);
            }
        }
    }
    int r0 = otile * 16 + gid, r1 = r0 + 8;
    float s0 = bg[r0] * rsqrtf(bv[r0] + 1e-5f);
    float h0 = (cb[r0] - bm[r0]) * s0 + bb[r0];
    float s1 = bg[r1] * rsqrtf(bv[r1] + 1e-5f);
    float h1 = (cb[r1] - bm[r1]) * s1 + bb[r1];
    size_t o0 = ((size_t)b * 64 + r0) * 784;
    size_t o1 = ((size_t)b * 64 + r1) * 784;
#pragma unroll
    for (int nf = 0; nf < 4; nf++) {
        int col = pxt + pxw + nf * 8 + 2 * tig;
        if (col < 784) {
            uint2 p0, p1;
            p0.x = packsplit(fmaxf(acc[nf][0] * s0 + h0, 0.f));
            p0.y = packsplit(fmaxf(acc[nf][1] * s0 + h0, 0.f));
            p1.x = packsplit(fmaxf(acc[nf][2] * s1 + h1, 0.f));
            p1.y = packsplit(fmaxf(acc[nf][3] * s1 + h1, 0.f));
            *reinterpret_cast<uint2*>(g_a2p + o0 + col) = p0;
            *reinterpret_cast<uint2*>(g_a2p + o1 + col) = p1;
        }
    }
}

// ---------------- conv3: 64->128, 3x3 s2 p1, 28 -> 14 (R13 exact) -----------
__global__ void __launch_bounds__(256) conv3_mma(
        const float* __restrict__ bg, const float* __restrict__ bb,
        const float* __restrict__ bm, const float* __restrict__ bv,
        const float* __restrict__ cb) {
    __shared__ __align__(16) uint4 sAh[2][8 * 66], sAl[2][8 * 66];
    __shared__ __align__(8) uint2 sBh[8 * 68], sBl[8 * 68];  // single buffer
    const int tid = threadIdx.x;
    const int b = blockIdx.y;
    const int pxt = blockIdx.x * 64;
    const int wid = tid >> 5, lane = tid & 31, gid = lane >> 2, tig = lane & 3;

    float acc[8][4];
#pragma unroll
    for (int n = 0; n < 8; n++)
#pragma unroll
        for (int j = 0; j < 4; j++) acc[n][j] = 0.f;

    const int pxl = tid & 63;
    const int ksl = tid >> 6;
    const int pxg = pxt + pxl;
    const int oh = pxg / 14, ow = pxg % 14;
    const int ihb = oh * 2 - 1, iwb = ow * 2 - 1;
    const unsigned* a2b = g_a2p + (size_t)b * 64 * 784;

    unsigned rp0[4], rp1[4];
    auto ldgB = [&](int c) {
        int t = c >> 1;
        int kh = (t * 11) >> 5;
        int kw = t - kh * 3;
        int ih = ihb + kh, iw = iwb + kw;
        bool okc = (unsigned)ih < 28u && (unsigned)iw < 28u;
        const unsigned* src = a2b + (c & 1) * 32 * 784 + ih * 28 + iw;
#pragma unroll
        for (int j = 0; j < 4; j++) {
            int k0 = ksl * 8 + 2 * j;
            rp0[j] = okc ? __ldg(src + (size_t)k0 * 784) : 0u;
            rp1[j] = okc ? __ldg(src + (size_t)(k0 + 1) * 784) : 0u;
        }
    };
    auto cpA = [&](int c, int buf) {
#pragma unroll
        for (int i = 0; i < 2; i++) {
            int e = tid + i * 256;
            cpa16(&sAh[buf][(e >> 6) * 66 + (e & 63)], g_w3p_h + c * 512 + e);
            cpa16(&sAl[buf][(e >> 6) * 66 + (e & 63)], g_w3p_l + c * 512 + e);
        }
    };

    ldgB(0);
    cpA(0, 0);
    CP_COMMIT();

    for (int c = 0; c < 18; c++) {
        const int buf = c & 1;
#pragma unroll
        for (int j = 0; j < 4; j++) {
            unsigned int hi2 = __byte_perm(rp0[j], rp1[j], 0x5410);
            unsigned int lo2 = __byte_perm(rp0[j], rp1[j], 0x7632);
            int row = (ksl >> 1) * 4 + j, reg = ksl & 1;
            ((unsigned int*)&sBh[row * 68 + pxl])[reg] = hi2;
            ((unsigned int*)&sBl[row * 68 + pxl])[reg] = lo2;
        }
        CP_WAIT0();
        __syncthreads();
        if (c < 17) {
            ldgB(c + 1);
            cpA(c + 1, buf ^ 1);
            CP_COMMIT();
        }
        const int tb = wid * 8 + gid;
#pragma unroll
        for (int step = 0; step < 2; step++) {
            int rb = step * 4 + tig;
            uint4 aH = sAh[buf][rb * 66 + tb];
            uint4 aL = sAl[buf][rb * 66 + tb];
#pragma unroll
            for (int nf = 0; nf < 8; nf++) {
                int col = nf * 8 + gid;
                uint2 bH = sBh[rb * 68 + col];
                uint2 bL = sBl[rb * 68 + col];
                MMA3F(acc[nf], aH, aL, bH, bL);
            }
        }
        __syncthreads();  // protect single B buffer before next STS
    }
    int r0 = wid * 16 + gid, r1 = r0 + 8;
    float s0 = bg[r0] * rsqrtf(bv[r0] + 1e-5f);
    float h0 = (cb[r0] - bm[r0]) * s0 + bb[r0];
    float s1 = bg[r1] * rsqrtf(bv[r1] + 1e-5f);
    float h1 = (cb[r1] - bm[r1]) * s1 + bb[r1];
    float* o0 = g_a3 + ((size_t)b * 128 + r0) * 196;
    float* o1 = g_a3 + ((size_t)b * 128 + r1) * 196;
#pragma unroll
    for (int nf = 0; nf < 8; nf++) {
        int col = pxt + nf * 8 + 2 * tig;
        if (col < 196) {
            float2 v0 = make_float2(fmaxf(acc[nf][0] * s0 + h0, 0.f),
                                    fmaxf(acc[nf][1] * s0 + h0, 0.f));
            float2 v1 = make_float2(fmaxf(acc[nf][2] * s1 + h1, 0.f),
                                    fmaxf(acc[nf][3] * s1 + h1, 0.f));
            *reinterpret_cast<float2*>(o0 + col) = v0;
            *reinterpret_cast<float2*>(o1 + col) = v1;
        }
    }
}

// ---------------- adaptive avgpool (2,2): 14x14 -> 2x2 ----------------------
__global__ void pool_kernel() {
    int idx = blockIdx.x * 256 + threadIdx.x;
    if (idx >= 128 * 512) return;
    int b = idx >> 9;
    int r = idx & 511;
    int c = r >> 2;
    int ph = (r >> 1) & 1;
    int pw = r & 1;
    const float* src = g_a3 + (((size_t)b * 128 + c) * 14 + ph * 7) * 14 + pw * 7;
    float s = 0.f;
#pragma unroll
    for (int h = 0; h < 7; h++)
#pragma unroll
        for (int w = 0; w < 7; w++) s += src[h * 14 + w];
    g_feat[idx] = s * (1.f / 49.f);
}

// ---------------- head: linear->tanh, quantum circuit, MLP ------------------
__global__ void head_kernel(const float* __restrict__ pre_w, const float* __restrict__ pre_b,
                            const float* __restrict__ qw,
                            const float* __restrict__ pw1, const float* __restrict__ pb1,
                            const float* __restrict__ pw2, const float* __restrict__ pb2,
                            float* __restrict__ out) {
    __shared__ float f_s[512];
    __shared__ float ang_s[4], q_s[4], h1_s[64];
    const int tid = threadIdx.x;
    const int b = blockIdx.x;

    for (int i = tid; i < 512; i += 128) f_s[i] = g_feat[b * 512 + i];
    __syncthreads();

    int wid = tid >> 5, lane = tid & 31;
    {
        float partial = 0.f;
        const float* wr = pre_w + wid * 512;
        for (int k = lane; k < 512; k += 32) partial += f_s[k] * wr[k];
#pragma unroll
        for (int o = 16; o > 0; o >>= 1) partial += __shfl_down_sync(0xffffffffu, partial, o);
        if (lane == 0) ang_s[wid] = tanhf(partial + pre_b[wid]) * 3.14159265358979323846f;
    }
    __syncthreads();

    if (tid == 0) {
        float sr[16], si[16];
        float cq[4], sq[4];
#pragma unroll
        for (int q = 0; q < 4; q++) {
            cq[q] = cosf(0.5f * ang_s[q]);
            sq[q] = sinf(0.5f * ang_s[q]);
        }
#pragma unroll
        for (int i = 0; i < 16; i++) {
            float vv = 1.f;
#pragma unroll
            for (int q = 0; q < 4; q++) vv *= ((i >> (3 - q)) & 1) ? sq[q] : cq[q];
            sr[i] = vv;
            si[i] = 0.f;
        }
        for (int l = 0; l < 2; l++) {
            for (int q = 0; q < 4; q++) {
                const int mk = 1 << (3 - q);
                const float* qwp = qw + (l * 4 + q) * 3;
                float c, s;
                c = cosf(0.5f * qwp[0]); s = sinf(0.5f * qwp[0]);
                for (int i = 0; i < 16; i++)
                    if (!(i & mk)) {
                        int j = i | mk;
                        float r0 = sr[i], i0 = si[i], r1 = sr[j], i1 = si[j];
                        sr[i] = c * r0 + s * i1;  si[i] = c * i0 - s * r1;
                        sr[j] = c * r1 + s * i0;  si[j] = c * i1 - s * r0;
                    }
                c = cosf(0.5f * qwp[1]); s = sinf(0.5f * qwp[1]);
                for (int i = 0; i < 16; i++)
                    if (!(i & mk)) {
                        int j = i | mk;
                        float r0 = sr[i], i0 = si[i], r1 = sr[j], i1 = si[j];
                        sr[i] = c * r0 - s * r1;  si[i] = c * i0 - s * i1;
                        sr[j] = s * r0 + c * r1;  si[j] = s * i0 + c * i1;
                    }
                c = cosf(0.5f * qwp[2]); s = sinf(0.5f * qwp[2]);
                for (int i = 0; i < 16; i++) {
                    float r = sr[i], im = si[i];
                    if (i & mk) { sr[i] = c * r - s * im; si[i] = c * im + s * r; }
                    else        { sr[i] = c * r + s * im; si[i] = c * im - s * r; }
                }
            }
            for (int e = 0; e < 4; e++) {
                int cm = 1 << (3 - e);
                int tm = 1 << (3 - ((e + 1) & 3));
                for (int i = 0; i < 16; i++)
                    if ((i & cm) && !(i & tm)) {
                        int j = i | tm;
                        float t = sr[i]; sr[i] = sr[j]; sr[j] = t;
                        t = si[i]; si[i] = si[j]; si[j] = t;
                    }
            }
        }
        for (int q = 0; q < 4; q++) {
            float z = 0.f;
            for (int i = 0; i < 16; i++) {
                float pp = sr[i] * sr[i] + si[i] * si[i];
                z += ((i >> (3 - q)) & 1) ? -pp : pp;
            }
            q_s[q] = z;
        }
    }
    __syncthreads();

    if (tid < 64) {
        float h = pb1[tid];
#pragma unroll
        for (int j = 0; j < 4; j++) h += q_s[j] * pw1[tid * 4 + j];
        h1_s[tid] = fmaxf(h, 0.f);
    }
    __syncthreads();

    if (tid < 5) {
        float o = pb2[tid];
        for (int k = 0; k < 64; k++) o += h1_s[k] * pw2[tid * 64 + k];
        out[b * 5 + tid] = o;
    }
}

// ---------------- launch ----------------------------------------------------
extern "C" void kernel_launch(void* const* d_in, const int* in_sizes, int n_in,
                              void* d_out, int out_size) {
    const float* x    = (const float*)d_in[0];
    const float* c1w  = (const float*)d_in[1];
    const float* c1b  = (const float*)d_in[2];
    const float* bn1g = (const float*)d_in[3];
    const float* bn1b = (const float*)d_in[4];
    const float* bn1m = (const float*)d_in[5];
    const float* bn1v = (const float*)d_in[6];
    const float* c2w  = (const float*)d_in[7];
    const float* c2b  = (const float*)d_in[8];
    const float* bn2g = (const float*)d_in[9];
    const float* bn2b = (const float*)d_in[10];
    const float* bn2m = (const float*)d_in[11];
    const float* bn2v = (const float*)d_in[12];
    const float* c3w  = (const float*)d_in[13];
    const float* c3b  = (const float*)d_in[14];
    const float* bn3g = (const float*)d_in[15];
    const float* bn3b = (const float*)d_in[16];
    const float* bn3m = (const float*)d_in[17];
    const float* bn3v = (const float*)d_in[18];
    const float* pre_w = (const float*)d_in[19];
    const float* pre_b = (const float*)d_in[20];
    const float* qw    = (const float*)d_in[21];
    const float* pw1   = (const float*)d_in[22];
    const float* pb1   = (const float*)d_in[23];
    const float* pw2   = (const float*)d_in[24];
    const float* pb2   = (const float*)d_in[25];
    float* out = (float*)d_out;

    prep_w<<<36, 256>>>(c1w, c2w, c3w);
    conv1_mma<<<dim3(25, 128), 256>>>(x, bn1g, bn1b, bn1m, bn1v, c1b);
    conv2_mma<<<dim3(13, 128), 256>>>(bn2g, bn2b, bn2m, bn2v, c2b);
    conv3_mma<<<dim3(4, 128), 256>>>(bn3g, bn3b, bn3m, bn3v, c3b);
    pool_kernel<<<256, 256>>>();
    head_kernel<<<128, 128>>>(pre_w, pre_b, qw, pw1, pb1, pw2, pb2, out);
}

// round 16
// speedup vs baseline: 1.1177x; 1.0928x over previous
#include <cuda_runtime.h>
#include <cuda_fp16.h>
#include <math.h>

// ---------------- intermediate buffers (device globals) ---------------------
__device__ unsigned int g_a1p[128 * 32 * 56 * 56];  // conv1 out, packed {hi,lo}
__device__ unsigned int g_a2p[128 * 64 * 28 * 28];  // conv2 out, packed {hi,lo}
__device__ float g_a3[128 * 128 * 14 * 14];         // conv3 out
__device__ float g_feat[128 * 512];                 // pooled features

// packed fp16 weight fragments (hi and lo planes), R13 layouts
__device__ uint4 g_w1p_h[7 * 8 * 16],  g_w1p_l[7 * 8 * 16];
__device__ uint4 g_w2p_h[9 * 8 * 32],  g_w2p_l[9 * 8 * 32];
__device__ uint4 g_w3p_h[18 * 8 * 64], g_w3p_l[18 * 8 * 64];

// ---------------- helpers ---------------------------------------------------
__device__ __forceinline__ void fsplit(float v, unsigned short& h, unsigned short& l) {
    __half hh = __float2half_rn(v);
    __half ll = __float2half_rn(v - __half2float(hh));
    h = __half_as_ushort(hh);
    l = __half_as_ushort(ll);
}
__device__ __forceinline__ unsigned int packsplit(float v) {
    unsigned short h, l;
    fsplit(v, h, l);
    return (unsigned)h | ((unsigned)l << 16);
}

#define MMAF(d, a, b0, b1)                                                      \
    asm volatile(                                                               \
        "mma.sync.aligned.m16n8k16.row.col.f32.f16.f16.f32 "                    \
        "{%0,%1,%2,%3}, {%4,%5,%6,%7}, {%8,%9}, {%0,%1,%2,%3};"                 \
        : "+f"(d[0]), "+f"(d[1]), "+f"(d[2]), "+f"(d[3])                        \
        : "r"(a.x), "r"(a.y), "r"(a.z), "r"(a.w), "r"(b0), "r"(b1))

#define MMA3F(acc, aH, aL, bH, bL)                                              \
    do {                                                                        \
        MMAF(acc, aH, bH.x, bH.y);                                              \
        MMAF(acc, aH, bL.x, bL.y);                                              \
        MMAF(acc, aL, bH.x, bH.y);                                              \
    } while (0)

__device__ __forceinline__ void cpa16(void* sdst, const void* gsrc) {
    unsigned s = (unsigned)__cvta_generic_to_shared(sdst);
    asm volatile("cp.async.cg.shared.global [%0], [%1], 16;"
                 :: "r"(s), "l"(gsrc) : "memory");
}
#define CP_COMMIT() asm volatile("cp.async.commit_group;" ::: "memory")
#define CP_WAIT0()  asm volatile("cp.async.wait_group 0;" ::: "memory")

// ---------------- weight prep (R13 exact) ------------------------------------
__device__ __forceinline__ void pack_frag(const float* v, uint4& H, uint4& L) {
    unsigned short h[8], l[8];
#pragma unroll
    for (int i = 0; i < 8; i++) fsplit(v[i], h[i], l[i]);
    H.x = h[0] | (h[1] << 16); H.y = h[2] | (h[3] << 16);
    H.z = h[4] | (h[5] << 16); H.w = h[6] | (h[7] << 16);
    L.x = l[0] | (l[1] << 16); L.y = l[2] | (l[3] << 16);
    L.z = l[4] | (l[5] << 16); L.w = l[6] | (l[7] << 16);
}

__global__ void prep_w(const float* __restrict__ w1, const float* __restrict__ w2,
                       const float* __restrict__ w3) {
    int i = blockIdx.x * 256 + threadIdx.x;
    if (i < 7 * 8 * 16) {
        int chunk = i >> 7, row = (i >> 4) & 7, t = i & 15;
        int tile = t >> 3, gid = t & 7;
        int step = row >> 2, tig = row & 3;
        int oc0 = tile * 16 + gid, oc1 = oc0 + 8;
        int kl = step * 16 + tig * 2;
        float u[8];
#pragma unroll
        for (int e = 0; e < 8; e++) {
            int oc = (e & 2) ? oc1 : oc0;
            int klx = kl + ((e >> 2) ? 8 : 0) + (e & 1);
            int kw = klx >> 2, ic = klx & 3;
            u[e] = (ic < 3 && kw < 7) ? w1[oc * 147 + ic * 49 + chunk * 7 + kw] : 0.f;
        }
        uint4 H, L;
        pack_frag(u, H, L);
        g_w1p_h[i] = H; g_w1p_l[i] = L;
    }
    if (i < 9 * 8 * 32) {
        int chunk = i >> 8, r = i & 255;
        int row = r >> 5, t = r & 31;
        int tile = t >> 3, gid = t & 7;
        int step = row >> 2, tig = row & 3;
        int oc0 = tile * 16 + gid, oc1 = oc0 + 8;
        int kl = step * 16 + tig * 2;
        float u[8];
#pragma unroll
        for (int e = 0; e < 8; e++) {
            int oc = (e & 2) ? oc1 : oc0;
            int klx = kl + ((e >> 2) ? 8 : 0) + (e & 1);
            u[e] = w2[oc * 288 + klx * 9 + chunk];
        }
        uint4 H, L;
        pack_frag(u, H, L);
        g_w2p_h[i] = H; g_w2p_l[i] = L;
    }
    if (i < 18 * 8 * 64) {
        int chunk = i >> 9, r = i & 511;
        int row = r >> 6, t = r & 63;
        int tile = t >> 3, gid = t & 7;
        int step = row >> 2, tig = row & 3;
        int oc0 = tile * 16 + gid, oc1 = oc0 + 8;
        int kl = step * 16 + tig * 2;
        int tap = chunk >> 1, icb = (chunk & 1) * 32;
        float u[8];
#pragma unroll
        for (int e = 0; e < 8; e++) {
            int oc = (e & 2) ? oc1 : oc0;
            int klx = kl + ((e >> 2) ? 8 : 0) + (e & 1);
            u[e] = w3[oc * 576 + (icb + klx) * 9 + tap];
        }
        uint4 H, L;
        pack_frag(u, H, L);
        g_w3p_h[i] = H; g_w3p_l[i] = L;
    }
}

// ---------------- conv1: 3->32, 7x7 s4 p3, 224 -> 56 (R13 exact) ------------
__global__ void __launch_bounds__(256) conv1_mma(
        const float* __restrict__ x,
        const float* __restrict__ bg, const float* __restrict__ bb,
        const float* __restrict__ bm, const float* __restrict__ bv,
        const float* __restrict__ cb) {
    __shared__ __align__(16) uint4 sAh[2][8 * 18], sAl[2][8 * 18];
    __shared__ __align__(8) uint2 sBh[2][8 * 132], sBl[2][8 * 132];
    const int tid = threadIdx.x;
    const int b = blockIdx.y;
    const int pxt = blockIdx.x * 128;
    const int wid = tid >> 5, lane = tid & 31, gid = lane >> 2, tig = lane & 3;
    const int otile = wid & 1;
    const int pxw = (wid >> 1) * 32;

    float acc[4][4];
#pragma unroll
    for (int n = 0; n < 4; n++)
#pragma unroll
        for (int j = 0; j < 4; j++) acc[n][j] = 0.f;

    const int pxl = tid & 127;
    const int ksl = tid >> 7;
    const int pxg = pxt + pxl;
    const int oh = pxg / 56, ow = pxg % 56;
    const int ihb = oh * 4 - 3, iwb = ow * 4 - 3;
    const float* xb = x + (size_t)b * 3 * 50176;

    float rv0[8], rv1[8];
    auto ldgB = [&](int c) {
        int ih = ihb + c;
        bool okh = (unsigned)ih < 224u;
        const float* xr = xb + ih * 224;
#pragma unroll
        for (int j = 0; j < 8; j++) {
            int k0 = ksl * 16 + 2 * j;
            int kw = k0 >> 2, ic = k0 & 3;
            int iw = iwb + kw;
            bool okp = okh && (unsigned)iw < 224u;
            rv0[j] = okp ? __ldg(xr + ic * 50176 + iw) : 0.f;
            rv1[j] = (okp && ic + 1 < 3) ? __ldg(xr + (ic + 1) * 50176 + iw) : 0.f;
        }
    };
    auto cpA = [&](int c, int buf) {
        if (tid < 128) {
            cpa16(&sAh[buf][(tid >> 4) * 18 + (tid & 15)], g_w1p_h + c * 128 + tid);
        } else {
            int e = tid - 128;
            cpa16(&sAl[buf][(e >> 4) * 18 + (e & 15)], g_w1p_l + c * 128 + e);
        }
    };

    ldgB(0);
    cpA(0, 0);
    CP_COMMIT();

    for (int c = 0; c < 7; c++) {
        const int buf = c & 1;
        CP_WAIT0();
#pragma unroll
        for (int j = 0; j < 8; j++) {
            unsigned short h0, l0, h1, l1;
            fsplit(rv0[j], h0, l0);
            fsplit(rv1[j], h1, l1);
            unsigned int hi2 = (unsigned)h0 | ((unsigned)h1 << 16);
            unsigned int lo2 = (unsigned)l0 | ((unsigned)l1 << 16);
            int row = ksl * 4 + (j & 3), reg = j >> 2;
            ((unsigned int*)&sBh[buf][row * 132 + pxl])[reg] = hi2;
            ((unsigned int*)&sBl[buf][row * 132 + pxl])[reg] = lo2;
        }
        __syncthreads();
        if (c < 6) {
            ldgB(c + 1);
            cpA(c + 1, buf ^ 1);
            CP_COMMIT();
        }
        const int tb = otile * 8 + gid;
#pragma unroll
        for (int step = 0; step < 2; step++) {
            int rb = step * 4 + tig;
            uint4 aH = sAh[buf][rb * 18 + tb];
            uint4 aL = sAl[buf][rb * 18 + tb];
#pragma unroll
            for (int nf = 0; nf < 4; nf++) {
                int col = pxw + nf * 8 + gid;
                uint2 bH = sBh[buf][rb * 132 + col];
                uint2 bL = sBl[buf][rb * 132 + col];
                MMA3F(acc[nf], aH, aL, bH, bL);
            }
        }
    }
    int r0 = otile * 16 + gid, r1 = r0 + 8;
    float s0 = bg[r0] * rsqrtf(bv[r0] + 1e-5f);
    float h0 = (cb[r0] - bm[r0]) * s0 + bb[r0];
    float s1 = bg[r1] * rsqrtf(bv[r1] + 1e-5f);
    float h1 = (cb[r1] - bm[r1]) * s1 + bb[r1];
    size_t o0 = ((size_t)b * 32 + r0) * 3136;
    size_t o1 = ((size_t)b * 32 + r1) * 3136;
#pragma unroll
    for (int nf = 0; nf < 4; nf++) {
        int col = pxt + pxw + nf * 8 + 2 * tig;
        if (col < 3136) {
            uint2 p0, p1;
            p0.x = packsplit(fmaxf(acc[nf][0] * s0 + h0, 0.f));
            p0.y = packsplit(fmaxf(acc[nf][1] * s0 + h0, 0.f));
            p1.x = packsplit(fmaxf(acc[nf][2] * s1 + h1, 0.f));
            p1.y = packsplit(fmaxf(acc[nf][3] * s1 + h1, 0.f));
            *reinterpret_cast<uint2*>(g_a1p + o0 + col) = p0;
            *reinterpret_cast<uint2*>(g_a1p + o1 + col) = p1;
        }
    }
}

// ---------------- conv2: 32->64, 3x3 s2 p1, 56 -> 28 (R13 exact) ------------
__global__ void __launch_bounds__(256) conv2_mma(
        const float* __restrict__ bg, const float* __restrict__ bb,
        const float* __restrict__ bm, const float* __restrict__ bv,
        const float* __restrict__ cb) {
    __shared__ __align__(16) uint4 sAh[2][8 * 34], sAl[2][8 * 34];
    __shared__ __align__(8) uint2 sBh[2][8 * 68], sBl[2][8 * 68];
    const int tid = threadIdx.x;
    const int b = blockIdx.y;
    const int pxt = blockIdx.x * 64;
    const int wid = tid >> 5, lane = tid & 31, gid = lane >> 2, tig = lane & 3;
    const int otile = wid & 3;
    const int pxw = (wid >> 2) * 32;

    float acc[4][4];
#pragma unroll
    for (int n = 0; n < 4; n++)
#pragma unroll
        for (int j = 0; j < 4; j++) acc[n][j] = 0.f;

    const int pxl = tid & 63;
    const int ksl = tid >> 6;
    const int pxg = pxt + pxl;
    const int oh = pxg / 28, ow = pxg % 28;
    const int ihb = oh * 2 - 1, iwb = ow * 2 - 1;
    const unsigned* a1b = g_a1p + (size_t)b * 32 * 3136;

    unsigned rp0[4], rp1[4];
    auto ldgB = [&](int c) {
        int kh = (c * 11) >> 5;
        int kw = c - kh * 3;
        int ih = ihb + kh, iw = iwb + kw;
        bool okc = (unsigned)ih < 56u && (unsigned)iw < 56u;
        const unsigned* src = a1b + ih * 56 + iw;
#pragma unroll
        for (int j = 0; j < 4; j++) {
            int k0 = ksl * 8 + 2 * j;
            rp0[j] = okc ? __ldg(src + (size_t)k0 * 3136) : 0u;
            rp1[j] = okc ? __ldg(src + (size_t)(k0 + 1) * 3136) : 0u;
        }
    };
    auto cpA = [&](int c, int buf) {
        cpa16(&sAh[buf][(tid >> 5) * 34 + (tid & 31)], g_w2p_h + c * 256 + tid);
        cpa16(&sAl[buf][(tid >> 5) * 34 + (tid & 31)], g_w2p_l + c * 256 + tid);
    };

    ldgB(0);
    cpA(0, 0);
    CP_COMMIT();

    for (int c = 0; c < 9; c++) {
        const int buf = c & 1;
        CP_WAIT0();
#pragma unroll
        for (int j = 0; j < 4; j++) {
            unsigned int hi2 = __byte_perm(rp0[j], rp1[j], 0x5410);
            unsigned int lo2 = __byte_perm(rp0[j], rp1[j], 0x7632);
            int row = (ksl >> 1) * 4 + j, reg = ksl & 1;
            ((unsigned int*)&sBh[buf][row * 68 + pxl])[reg] = hi2;
            ((unsigned int*)&sBl[buf][row * 68 + pxl])[reg] = lo2;
        }
        __syncthreads();
        if (c < 8) {
            ldgB(c + 1);
            cpA(c + 1, buf ^ 1);
            CP_COMMIT();
        }
        const int tb = otile * 8 + gid;
#pragma unroll
        for (int step = 0; step < 2; step++) {
            int rb = step * 4 + tig;
            uint4 aH = sAh[buf][rb * 34 + tb];
            uint4 aL = sAl[buf][rb * 34 + tb];
#pragma unroll
            for (int nf = 0; nf < 4; nf++) {
                int col = pxw + nf * 8 + gid;
                uint2 bH = sBh[buf][rb * 68 + col];
                uint2 bL = sBl[buf][rb * 68 + col];
                MMA3F(acc[nf], aH, aL, bH, bL);
            }
        }
    }
    int r0 = otile * 16 + gid, r1 = r0 + 8;
    float s0 = bg[r0] * rsqrtf(bv[r0] + 1e-5f);
    float h0 = (cb[r0] - bm[r0]) * s0 + bb[r0];
    float s1 = bg[r1] * rsqrtf(bv[r1] + 1e-5f);
    float h1 = (cb[r1] - bm[r1]) * s1 + bb[r1];
    size_t o0 = ((size_t)b * 64 + r0) * 784;
    size_t o1 = ((size_t)b * 64 + r1) * 784;
#pragma unroll
    for (int nf = 0; nf < 4; nf++) {
        int col = pxt + pxw + nf * 8 + 2 * tig;
        if (col < 784) {
            uint2 p0, p1;
            p0.x = packsplit(fmaxf(acc[nf][0] * s0 + h0, 0.f));
            p0.y = packsplit(fmaxf(acc[nf][1] * s0 + h0, 0.f));
            p1.x = packsplit(fmaxf(acc[nf][2] * s1 + h1, 0.f));
            p1.y = packsplit(fmaxf(acc[nf][3] * s1 + h1, 0.f));
            *reinterpret_cast<uint2*>(g_a2p + o0 + col) = p0;
            *reinterpret_cast<uint2*>(g_a2p + o1 + col) = p1;
        }
    }
}

// ---------------- conv3: 64->128, 3x3 s2 p1, 28 -> 14 (32oc x 32px tiles) ---
__global__ void __launch_bounds__(256) conv3_mma(
        const float* __restrict__ bg, const float* __restrict__ bb,
        const float* __restrict__ bm, const float* __restrict__ bv,
        const float* __restrict__ cb) {
    __shared__ __align__(16) uint4 sAh[2][8 * 66], sAl[2][8 * 66];
    __shared__ __align__(8) uint2 sBh[8 * 68], sBl[8 * 68];  // single buffer
    const int tid = threadIdx.x;
    const int b = blockIdx.y;
    const int pxt = blockIdx.x * 64;
    const int wid = tid >> 5, lane = tid & 31, gid = lane >> 2, tig = lane & 3;
    const int ocg = wid & 3;       // 4 oc-groups of 32
    const int pxgp = wid >> 2;     // 2 px-groups of 32

    float acc[2][4][4];
#pragma unroll
    for (int o = 0; o < 2; o++)
#pragma unroll
        for (int n = 0; n < 4; n++)
#pragma unroll
            for (int j = 0; j < 4; j++) acc[o][n][j] = 0.f;

    const int pxl = tid & 63;
    const int ksl = tid >> 6;
    const int pxg = pxt + pxl;
    const int oh = pxg / 14, ow = pxg % 14;
    const int ihb = oh * 2 - 1, iwb = ow * 2 - 1;
    const unsigned* a2b = g_a2p + (size_t)b * 64 * 784;

    unsigned rp0[4], rp1[4];
    auto ldgB = [&](int c) {
        int t = c >> 1;
        int kh = (t * 11) >> 5;
        int kw = t - kh * 3;
        int ih = ihb + kh, iw = iwb + kw;
        bool okc = (unsigned)ih < 28u && (unsigned)iw < 28u;
        const unsigned* src = a2b + (c & 1) * 32 * 784 + ih * 28 + iw;
#pragma unroll
        for (int j = 0; j < 4; j++) {
            int k0 = ksl * 8 + 2 * j;
            rp0[j] = okc ? __ldg(src + (size_t)k0 * 784) : 0u;
            rp1[j] = okc ? __ldg(src + (size_t)(k0 + 1) * 784) : 0u;
        }
    };
    auto cpA = [&](int c, int buf) {
#pragma unroll
        for (int i = 0; i < 2; i++) {
            int e = tid + i * 256;
            cpa16(&sAh[buf][(e >> 6) * 66 + (e & 63)], g_w3p_h + c * 512 + e);
            cpa16(&sAl[buf][(e >> 6) * 66 + (e & 63)], g_w3p_l + c * 512 + e);
        }
    };

    ldgB(0);
    cpA(0, 0);
    CP_COMMIT();

    for (int c = 0; c < 18; c++) {
        const int buf = c & 1;
#pragma unroll
        for (int j = 0; j < 4; j++) {
            unsigned int hi2 = __byte_perm(rp0[j], rp1[j], 0x5410);
            unsigned int lo2 = __byte_perm(rp0[j], rp1[j], 0x7632);
            int row = (ksl >> 1) * 4 + j, reg = ksl & 1;
            ((unsigned int*)&sBh[row * 68 + pxl])[reg] = hi2;
            ((unsigned int*)&sBl[row * 68 + pxl])[reg] = lo2;
        }
        CP_WAIT0();
        __syncthreads();
        if (c < 17) {
            ldgB(c + 1);
            cpA(c + 1, buf ^ 1);
            CP_COMMIT();
        }
#pragma unroll
        for (int step = 0; step < 2; step++) {
            int rb = step * 4 + tig;
            uint4 aH0 = sAh[buf][rb * 66 + (ocg * 2 + 0) * 8 + gid];
            uint4 aL0 = sAl[buf][rb * 66 + (ocg * 2 + 0) * 8 + gid];
            uint4 aH1 = sAh[buf][rb * 66 + (ocg * 2 + 1) * 8 + gid];
            uint4 aL1 = sAl[buf][rb * 66 + (ocg * 2 + 1) * 8 + gid];
#pragma unroll
            for (int nf = 0; nf < 4; nf++) {
                int col = pxgp * 32 + nf * 8 + gid;
                uint2 bH = sBh[rb * 68 + col];
                uint2 bL = sBl[rb * 68 + col];
                MMA3F(acc[0][nf], aH0, aL0, bH, bL);
                MMA3F(acc[1][nf], aH1, aL1, bH, bL);
            }
        }
        __syncthreads();  // protect single B buffer before next STS
    }
#pragma unroll
    for (int o = 0; o < 2; o++) {
        int r0 = ocg * 32 + o * 16 + gid, r1 = r0 + 8;
        float s0 = bg[r0] * rsqrtf(bv[r0] + 1e-5f);
        float h0 = (cb[r0] - bm[r0]) * s0 + bb[r0];
        float s1 = bg[r1] * rsqrtf(bv[r1] + 1e-5f);
        float h1 = (cb[r1] - bm[r1]) * s1 + bb[r1];
        float* o0 = g_a3 + ((size_t)b * 128 + r0) * 196;
        float* o1 = g_a3 + ((size_t)b * 128 + r1) * 196;
#pragma unroll
        for (int nf = 0; nf < 4; nf++) {
            int col = pxt + pxgp * 32 + nf * 8 + 2 * tig;
            if (col < 196) {
                float2 v0 = make_float2(fmaxf(acc[o][nf][0] * s0 + h0, 0.f),
                                        fmaxf(acc[o][nf][1] * s0 + h0, 0.f));
                float2 v1 = make_float2(fmaxf(acc[o][nf][2] * s1 + h1, 0.f),
                                        fmaxf(acc[o][nf][3] * s1 + h1, 0.f));
                *reinterpret_cast<float2*>(o0 + col) = v0;
                *reinterpret_cast<float2*>(o1 + col) = v1;
            }
        }
    }
}

// ---------------- adaptive avgpool (2,2): 14x14 -> 2x2 ----------------------
__global__ void pool_kernel() {
    int idx = blockIdx.x * 256 + threadIdx.x;
    if (idx >= 128 * 512) return;
    int b = idx >> 9;
    int r = idx & 511;
    int c = r >> 2;
    int ph = (r >> 1) & 1;
    int pw = r & 1;
    const float* src = g_a3 + (((size_t)b * 128 + c) * 14 + ph * 7) * 14 + pw * 7;
    float s = 0.f;
#pragma unroll
    for (int h = 0; h < 7; h++)
#pragma unroll
        for (int w = 0; w < 7; w++) s += src[h * 14 + w];
    g_feat[idx] = s * (1.f / 49.f);
}

// ---------------- head: linear->tanh, quantum circuit, MLP ------------------
__global__ void head_kernel(const float* __restrict__ pre_w, const float* __restrict__ pre_b,
                            const float* __restrict__ qw,
                            const float* __restrict__ pw1, const float* __restrict__ pb1,
                            const float* __restrict__ pw2, const float* __restrict__ pb2,
                            float* __restrict__ out) {
    __shared__ float f_s[512];
    __shared__ float ang_s[4], q_s[4], h1_s[64];
    const int tid = threadIdx.x;
    const int b = blockIdx.x;

    for (int i = tid; i < 512; i += 128) f_s[i] = g_feat[b * 512 + i];
    __syncthreads();

    int wid = tid >> 5, lane = tid & 31;
    {
        float partial = 0.f;
        const float* wr = pre_w + wid * 512;
        for (int k = lane; k < 512; k += 32) partial += f_s[k] * wr[k];
#pragma unroll
        for (int o = 16; o > 0; o >>= 1) partial += __shfl_down_sync(0xffffffffu, partial, o);
        if (lane == 0) ang_s[wid] = tanhf(partial + pre_b[wid]) * 3.14159265358979323846f;
    }
    __syncthreads();

    if (tid == 0) {
        float sr[16], si[16];
        float cq[4], sq[4];
#pragma unroll
        for (int q = 0; q < 4; q++) {
            cq[q] = cosf(0.5f * ang_s[q]);
            sq[q] = sinf(0.5f * ang_s[q]);
        }
#pragma unroll
        for (int i = 0; i < 16; i++) {
            float vv = 1.f;
#pragma unroll
            for (int q = 0; q < 4; q++) vv *= ((i >> (3 - q)) & 1) ? sq[q] : cq[q];
            sr[i] = vv;
            si[i] = 0.f;
        }
        for (int l = 0; l < 2; l++) {
            for (int q = 0; q < 4; q++) {
                const int mk = 1 << (3 - q);
                const float* qwp = qw + (l * 4 + q) * 3;
                float c, s;
                c = cosf(0.5f * qwp[0]); s = sinf(0.5f * qwp[0]);
                for (int i = 0; i < 16; i++)
                    if (!(i & mk)) {
                        int j = i | mk;
                        float r0 = sr[i], i0 = si[i], r1 = sr[j], i1 = si[j];
                        sr[i] = c * r0 + s * i1;  si[i] = c * i0 - s * r1;
                        sr[j] = c * r1 + s * i0;  si[j] = c * i1 - s * r0;
                    }
                c = cosf(0.5f * qwp[1]); s = sinf(0.5f * qwp[1]);
                for (int i = 0; i < 16; i++)
                    if (!(i & mk)) {
                        int j = i | mk;
                        float r0 = sr[i], i0 = si[i], r1 = sr[j], i1 = si[j];
                        sr[i] = c * r0 - s * r1;  si[i] = c * i0 - s * i1;
                        sr[j] = s * r0 + c * r1;  si[j] = s * i0 + c * i1;
                    }
                c = cosf(0.5f * qwp[2]); s = sinf(0.5f * qwp[2]);
                for (int i = 0; i < 16; i++) {
                    float r = sr[i], im = si[i];
                    if (i & mk) { sr[i] = c * r - s * im; si[i] = c * im + s * r; }
                    else        { sr[i] = c * r + s * im; si[i] = c * im - s * r; }
                }
            }
            for (int e = 0; e < 4; e++) {
                int cm = 1 << (3 - e);
                int tm = 1 << (3 - ((e + 1) & 3));
                for (int i = 0; i < 16; i++)
                    if ((i & cm) && !(i & tm)) {
                        int j = i | tm;
                        float t = sr[i]; sr[i] = sr[j]; sr[j] = t;
                        t = si[i]; si[i] = si[j]; si[j] = t;
                    }
            }
        }
        for (int q = 0; q < 4; q++) {
            float z = 0.f;
            for (int i = 0; i < 16; i++) {
                float pp = sr[i] * sr[i] + si[i] * si[i];
                z += ((i >> (3 - q)) & 1) ? -pp : pp;
            }
            q_s[q] = z;
        }
    }
    __syncthreads();

    if (tid < 64) {
        float h = pb1[tid];
#pragma unroll
        for (int j = 0; j < 4; j++) h += q_s[j] * pw1[tid * 4 + j];
        h1_s[tid] = fmaxf(h, 0.f);
    }
    __syncthreads();

    if (tid < 5) {
        float o = pb2[tid];
        for (int k = 0; k < 64; k++) o += h1_s[k] * pw2[tid * 64 + k];
        out[b * 5 + tid] = o;
    }
}

// ---------------- launch ----------------------------------------------------
extern "C" void kernel_launch(void* const* d_in, const int* in_sizes, int n_in,
                              void* d_out, int out_size) {
    const float* x    = (const float*)d_in[0];
    const float* c1w  = (const float*)d_in[1];
    const float* c1b  = (const float*)d_in[2];
    const float* bn1g = (const float*)d_in[3];
    const float* bn1b = (const float*)d_in[4];
    const float* bn1m = (const float*)d_in[5];
    const float* bn1v = (const float*)d_in[6];
    const float* c2w  = (const float*)d_in[7];
    const float* c2b  = (const float*)d_in[8];
    const float* bn2g = (const float*)d_in[9];
    const float* bn2b = (const float*)d_in[10];
    const float* bn2m = (const float*)d_in[11];
    const float* bn2v = (const float*)d_in[12];
    const float* c3w  = (const float*)d_in[13];
    const float* c3b  = (const float*)d_in[14];
    const float* bn3g = (const float*)d_in[15];
    const float* bn3b = (const float*)d_in[16];
    const float* bn3m = (const float*)d_in[17];
    const float* bn3v = (const float*)d_in[18];
    const float* pre_w = (const float*)d_in[19];
    const float* pre_b = (const float*)d_in[20];
    const float* qw    = (const float*)d_in[21];
    const float* pw1   = (const float*)d_in[22];
    const float* pb1   = (const float*)d_in[23];
    const float* pw2   = (const float*)d_in[24];
    const float* pb2   = (const float*)d_in[25];
    float* out = (float*)d_out;

    prep_w<<<36, 256>>>(c1w, c2w, c3w);
    conv1_mma<<<dim3(25, 128), 256>>>(x, bn1g, bn1b, bn1m, bn1v, c1b);
    conv2_mma<<<dim3(13, 128), 256>>>(bn2g, bn2b, bn2m, bn2v, c2b);
    conv3_mma<<<dim3(4, 128), 256>>>(bn3g, bn3b, bn3m, bn3v, c3b);
    pool_kernel<<<256, 256>>>();
    head_kernel<<<128, 128>>>(pre_w, pre_b, qw, pw1, pb1, pw2, pb2, out);
}